// round 3
// baseline (speedup 1.0000x reference)
#include <cuda_runtime.h>
#include <cstdint>

// FeatureVolume: trilinear grid_sample of fm [32, 129, 129, 129] at 1M coords in [-1,1].
// Strategy: per-launch transpose fm -> channel-last [D,H,W,C] scratch (1 cache line
// per corner), then gather with 8 threads/point (float4 = 4 channels each).

#define FV_S   129
#define FV_DHW (129 * 129 * 129)   // 2,146,689 voxels
#define FV_C   32

// Channel-last scratch volume: 2,146,689 * 32 floats = ~262 MB (device bss).
__device__ float g_fmT[(size_t)FV_DHW * FV_C];

// ---------------------------------------------------------------------------
// Transpose [C, DHW] -> [DHW, C], both sides coalesced via a 32x32 smem tile.
// Block: 32x8 threads; each block handles one 32-voxel slab across all 32 channels.
// ---------------------------------------------------------------------------
__global__ void fv_transpose_kernel(const float* __restrict__ fm) {
    __shared__ float tile[32][33];          // +1 pad: conflict-free transpose
    const int v0 = blockIdx.x * 32;
    const int tx = threadIdx.x;             // 0..31
    const int ty = threadIdx.y;             // 0..7

    // Load: tile[c][vloc] <- fm[c * DHW + v0 + vloc]; coalesced along voxels.
    #pragma unroll
    for (int i = 0; i < 4; i++) {
        const int c = ty + i * 8;
        const int v = v0 + tx;
        tile[c][tx] = (v < FV_DHW) ? fm[(size_t)c * FV_DHW + v] : 0.0f;
    }
    __syncthreads();

    // Store: g_fmT[v * 32 + c]; 32 consecutive channels = 128B coalesced.
    #pragma unroll
    for (int i = 0; i < 4; i++) {
        const int vloc = ty + i * 8;
        const int v = v0 + vloc;
        if (v < FV_DHW) g_fmT[(size_t)v * FV_C + tx] = tile[tx][vloc];
    }
}

// Accumulate one corner: v4 load (one LDG.128) scaled by trilinear weight.
static __device__ __forceinline__ void fv_acc_corner(
    float4& acc, const float4* __restrict__ f, int vox, float wgt
) {
    const float4 v4 = __ldg(&f[(size_t)vox * 8]);
    acc.x = fmaf(wgt, v4.x, acc.x);
    acc.y = fmaf(wgt, v4.y, acc.y);
    acc.z = fmaf(wgt, v4.z, acc.z);
    acc.w = fmaf(wgt, v4.w, acc.w);
}

// ---------------------------------------------------------------------------
// Sample: 8 threads per point; thread g in [0,8) owns channels [4g, 4g+4) as a
// float4. Each corner is one LDG.128; the 8-thread group covers the full 128B
// line of that corner. Output store is a coalesced STG.128.
// Coords are loaded once per point (3 lanes of the 8-lane group) and broadcast
// with __shfl_sync.
// ---------------------------------------------------------------------------
__global__ __launch_bounds__(256) void fv_sample_kernel(
    const float* __restrict__ xs,   // [N, 3] coords
    float4* __restrict__ out,       // [N, 8] float4 == [N, 32] float
    int n
) {
    const int t    = blockIdx.x * blockDim.x + threadIdx.x;
    const int p    = t >> 3;
    const int g    = t & 7;                 // channel group within point
    const int lane = threadIdx.x & 31;
    const int base = lane & ~7;             // first lane of this point's group

    // Cooperative coord load: lane r in [0,3) of each group loads component r.
    float cload = 0.0f;
    if (p < n && g < 3) cload = __ldg(xs + 3 * (size_t)p + g);
    const float cx = __shfl_sync(0xffffffffu, cload, base + 0);  // -> W
    const float cy = __shfl_sync(0xffffffffu, cload, base + 1);  // -> H
    const float cz = __shfl_sync(0xffffffffu, cload, base + 2);  // -> D
    if (p >= n) return;

    // align_corners=True, border padding: i = clamp((c+1)*0.5*(S-1), 0, S-1)
    const float fx = fminf(fmaxf((cx + 1.0f) * 64.0f, 0.0f), 128.0f);
    const float fy = fminf(fmaxf((cy + 1.0f) * 64.0f, 0.0f), 128.0f);
    const float fz = fminf(fmaxf((cz + 1.0f) * 64.0f, 0.0f), 128.0f);

    const int x0 = (int)floorf(fx);
    const int y0 = (int)floorf(fy);
    const int z0 = (int)floorf(fz);
    const float tx = fx - (float)x0;
    const float ty = fy - (float)y0;
    const float tz = fz - (float)z0;
    const int x1 = min(x0 + 1, 128);
    const int y1 = min(y0 + 1, 128);
    const int z1 = min(z0 + 1, 128);

    const float wx0 = 1.0f - tx, wx1 = tx;
    const float wy0 = 1.0f - ty, wy1 = ty;
    const float wz0 = 1.0f - tz, wz1 = tz;

    // Row bases in voxel units: voxel(z,y,x) = (z*129 + y)*129 + x
    const int r00 = (z0 * FV_S + y0) * FV_S;
    const int r01 = (z0 * FV_S + y1) * FV_S;
    const int r10 = (z1 * FV_S + y0) * FV_S;
    const int r11 = (z1 * FV_S + y1) * FV_S;

    // float4 view offset by this thread's channel group.
    const float4* __restrict__ f = reinterpret_cast<const float4*>(g_fmT) + g;

    float4 acc = make_float4(0.0f, 0.0f, 0.0f, 0.0f);

    fv_acc_corner(acc, f, r00 + x0, wz0 * wy0 * wx0);
    fv_acc_corner(acc, f, r00 + x1, wz0 * wy0 * wx1);
    fv_acc_corner(acc, f, r01 + x0, wz0 * wy1 * wx0);
    fv_acc_corner(acc, f, r01 + x1, wz0 * wy1 * wx1);
    fv_acc_corner(acc, f, r10 + x0, wz1 * wy0 * wx0);
    fv_acc_corner(acc, f, r10 + x1, wz1 * wy0 * wx1);
    fv_acc_corner(acc, f, r11 + x0, wz1 * wy1 * wx0);
    fv_acc_corner(acc, f, r11 + x1, wz1 * wy1 * wx1);

    out[(size_t)p * 8 + g] = acc;
}

extern "C" void kernel_launch(void* const* d_in, const int* in_sizes, int n_in,
                              void* d_out, int out_size) {
    const float* x  = (const float*)d_in[0];   // [N, 3]
    const float* fm = (const float*)d_in[1];   // [32, 129, 129, 129]
    const int n = in_sizes[0] / 3;

    // 1) Transpose to channel-last scratch (runs every replay; deterministic).
    fv_transpose_kernel<<<(FV_DHW + 31) / 32, dim3(32, 8)>>>(fm);

    // 2) Gather + trilinear blend. 8 threads per point.
    const int total = n * 8;
    fv_sample_kernel<<<(total + 255) / 256, 256>>>(x, (float4*)d_out, n);
}

// round 9
// speedup vs baseline: 1.4195x; 1.4195x over previous
#include <cuda_runtime.h>
#include <cuda_fp16.h>
#include <cstdint>

// FeatureVolume: trilinear grid_sample of fm [32, 129, 129, 129] at 1M coords in [-1,1].
// R3 measured both phases pinned to the HBM roofline (5993 GB/s) -> only lever is
// fewer bytes. This round: fp16 channel-last scratch (131 MB ~= L2-resident).
// Corner = 64B; each of the 8 threads/point loads 8B (4 fp16 channels), fp32 math.

#define FV_S   129
#define FV_DHW (129 * 129 * 129)   // 2,146,689 voxels
#define FV_C   32

// Channel-last fp16 scratch: 2,146,689 * 32 * 2B = ~131 MB (device bss).
__device__ __half g_fmT[(size_t)FV_DHW * FV_C];

// ---------------------------------------------------------------------------
// Transpose [C, DHW] fp32 -> [DHW, C] fp16 via a 32x32 smem tile.
// Block 32x8. Store phase: all 32 lanes active, each writes one half2
// (2 channels) for one of 2 voxels -> 64B contiguous per voxel.
// ---------------------------------------------------------------------------
__global__ void fv_transpose_kernel(const float* __restrict__ fm) {
    __shared__ float tile[32][33];          // +1 pad
    const int v0 = blockIdx.x * 32;
    const int tx = threadIdx.x;             // 0..31
    const int ty = threadIdx.y;             // 0..7

    // Load: tile[c][vloc] <- fm[c * DHW + v0 + vloc]; coalesced along voxels.
    #pragma unroll
    for (int i = 0; i < 4; i++) {
        const int c = ty + i * 8;
        const int v = v0 + tx;
        tile[c][tx] = (v < FV_DHW) ? fm[(size_t)c * FV_DHW + v] : 0.0f;
    }
    __syncthreads();

    // Store: g_fmT[v*32 + 2*c2 .. 2*c2+1] as half2. Lane tx: voxel-half select
    // (tx>>4) and channel pair (tx&15); 2 voxels per iteration, 4 warps x 8 ty.
    __half2* __restrict__ outp = reinterpret_cast<__half2*>(g_fmT);
    #pragma unroll
    for (int i = 0; i < 2; i++) {
        const int vloc = ty + i * 16 + ((tx >> 4) << 3);
        const int c2   = tx & 15;
        const int v    = v0 + vloc;
        if (v < FV_DHW) {
            const float2 f2 = make_float2(tile[2 * c2][vloc], tile[2 * c2 + 1][vloc]);
            outp[(size_t)v * 16 + c2] = __float22half2_rn(f2);
        }
    }
}

// Accumulate one corner: 8B load (4 fp16 channels), fp32 fmaf.
static __device__ __forceinline__ void fv_acc_corner(
    float4& acc, const uint2* __restrict__ f, int vox, float wgt
) {
    uint2 u = __ldg(&f[(size_t)vox * 8]);
    const __half2 h0 = *reinterpret_cast<const __half2*>(&u.x);
    const __half2 h1 = *reinterpret_cast<const __half2*>(&u.y);
    const float2 a = __half22float2(h0);
    const float2 b = __half22float2(h1);
    acc.x = fmaf(wgt, a.x, acc.x);
    acc.y = fmaf(wgt, a.y, acc.y);
    acc.z = fmaf(wgt, b.x, acc.z);
    acc.w = fmaf(wgt, b.y, acc.w);
}

// ---------------------------------------------------------------------------
// Sample: 8 threads per point; thread g owns channels [4g, 4g+4). Each corner:
// one LDG.64 per thread; the 8-thread group covers the 64B corner record.
// Output: coalesced STG.128 (fp32). Coords loaded once per point + shfl bcast.
// ---------------------------------------------------------------------------
__global__ __launch_bounds__(256) void fv_sample_kernel(
    const float* __restrict__ xs,   // [N, 3] coords
    float4* __restrict__ out,       // [N, 8] float4 == [N, 32] float
    int n
) {
    const int t    = blockIdx.x * blockDim.x + threadIdx.x;
    const int p    = t >> 3;
    const int g    = t & 7;                 // channel group within point
    const int lane = threadIdx.x & 31;
    const int base = lane & ~7;             // first lane of this point's group

    // Cooperative coord load: lane r in [0,3) of each group loads component r.
    float cload = 0.0f;
    if (p < n && g < 3) cload = __ldg(xs + 3 * (size_t)p + g);
    const float cx = __shfl_sync(0xffffffffu, cload, base + 0);  // -> W
    const float cy = __shfl_sync(0xffffffffu, cload, base + 1);  // -> H
    const float cz = __shfl_sync(0xffffffffu, cload, base + 2);  // -> D
    if (p >= n) return;

    // align_corners=True, border padding: i = clamp((c+1)*0.5*(S-1), 0, S-1)
    const float fx = fminf(fmaxf((cx + 1.0f) * 64.0f, 0.0f), 128.0f);
    const float fy = fminf(fmaxf((cy + 1.0f) * 64.0f, 0.0f), 128.0f);
    const float fz = fminf(fmaxf((cz + 1.0f) * 64.0f, 0.0f), 128.0f);

    const int x0 = (int)floorf(fx);
    const int y0 = (int)floorf(fy);
    const int z0 = (int)floorf(fz);
    const float tx = fx - (float)x0;
    const float ty = fy - (float)y0;
    const float tz = fz - (float)z0;
    const int x1 = min(x0 + 1, 128);
    const int y1 = min(y0 + 1, 128);
    const int z1 = min(z0 + 1, 128);

    const float wx0 = 1.0f - tx, wx1 = tx;
    const float wy0 = 1.0f - ty, wy1 = ty;
    const float wz0 = 1.0f - tz, wz1 = tz;

    // Row bases in voxel units: voxel(z,y,x) = (z*129 + y)*129 + x
    const int r00 = (z0 * FV_S + y0) * FV_S;
    const int r01 = (z0 * FV_S + y1) * FV_S;
    const int r10 = (z1 * FV_S + y0) * FV_S;
    const int r11 = (z1 * FV_S + y1) * FV_S;

    // uint2 (8B = 4 fp16) view offset by this thread's channel group.
    const uint2* __restrict__ f = reinterpret_cast<const uint2*>(g_fmT) + g;

    float4 acc = make_float4(0.0f, 0.0f, 0.0f, 0.0f);

    fv_acc_corner(acc, f, r00 + x0, wz0 * wy0 * wx0);
    fv_acc_corner(acc, f, r00 + x1, wz0 * wy0 * wx1);
    fv_acc_corner(acc, f, r01 + x0, wz0 * wy1 * wx0);
    fv_acc_corner(acc, f, r01 + x1, wz0 * wy1 * wx1);
    fv_acc_corner(acc, f, r10 + x0, wz1 * wy0 * wx0);
    fv_acc_corner(acc, f, r10 + x1, wz1 * wy0 * wx1);
    fv_acc_corner(acc, f, r11 + x0, wz1 * wy1 * wx0);
    fv_acc_corner(acc, f, r11 + x1, wz1 * wy1 * wx1);

    out[(size_t)p * 8 + g] = acc;
}

extern "C" void kernel_launch(void* const* d_in, const int* in_sizes, int n_in,
                              void* d_out, int out_size) {
    const float* x  = (const float*)d_in[0];   // [N, 3]
    const float* fm = (const float*)d_in[1];   // [32, 129, 129, 129]
    const int n = in_sizes[0] / 3;

    // 1) Transpose + fp16 quantize to channel-last scratch (every replay).
    fv_transpose_kernel<<<(FV_DHW + 31) / 32, dim3(32, 8)>>>(fm);

    // 2) Gather + trilinear blend. 8 threads per point.
    const int total = n * 8;
    fv_sample_kernel<<<(total + 255) / 256, 256>>>(x, (float4*)d_out, n);
}

// round 11
// speedup vs baseline: 1.6187x; 1.1403x over previous
#include <cuda_runtime.h>
#include <cuda_fp16.h>
#include <cstdint>

// FeatureVolume: trilinear grid_sample of fm [32, 129, 129, 129] at 1M coords in [-1,1].
// R9 measured: total 178.7us (transpose ~83.7us @4.7TB/s, sample 94.9us still 74% DRAM
// => volume NOT staying L2-resident; out-stream evicts it). This round:
//  (1) __stcs streaming stores for the output (evict-first; protect volume in L2)
//  (2) transpose with 4x work per block (128-voxel tiles) to close the 4.7->6 TB/s gap.

#define FV_S   129
#define FV_DHW (129 * 129 * 129)   // 2,146,689 voxels
#define FV_C   32
#define TVOX   128                 // voxels per transpose block

// Channel-last fp16 scratch: 2,146,689 * 32 * 2B = ~131 MB (device bss).
__device__ __half g_fmT[(size_t)FV_DHW * FV_C];

// ---------------------------------------------------------------------------
// Transpose [C, DHW] fp32 -> [DHW, C] fp16 via a 32ch x 128vox smem tile.
// Block 32x8 (256 thr): 16 coalesced 128B loads + 8 half2 stores per thread.
// ---------------------------------------------------------------------------
__global__ __launch_bounds__(256) void fv_transpose_kernel(const float* __restrict__ fm) {
    __shared__ float tile[32][TVOX + 1];    // +1 pad
    const int v0 = blockIdx.x * TVOX;
    const int tx = threadIdx.x;             // 0..31
    const int ty = threadIdx.y;             // 0..7

    // Load: tile[c][vloc] <- fm[c*DHW + v0+vloc]; 128B coalesced per warp.
    #pragma unroll
    for (int i = 0; i < 4; i++) {
        const int c = ty + i * 8;
        #pragma unroll
        for (int j = 0; j < 4; j++) {
            const int vloc = tx + 32 * j;
            const int v = v0 + vloc;
            tile[c][vloc] = (v < FV_DHW) ? fm[(size_t)c * FV_DHW + v] : 0.0f;
        }
    }
    __syncthreads();

    // Store: g_fmT[v*32 + 2*c2 .. 2*c2+1] as half2. Lanes 0-15 cover one voxel's
    // 16 channel-pairs (64B contiguous), lanes 16-31 a second voxel.
    __half2* __restrict__ outp = reinterpret_cast<__half2*>(g_fmT);
    const int c2 = tx & 15;
    const int vh = tx >> 4;                 // 0 or 1
    #pragma unroll
    for (int s = 0; s < 4; s++) {
        #pragma unroll
        for (int i = 0; i < 2; i++) {
            const int vloc = s * 32 + ty + i * 16 + (vh << 3);
            const int v = v0 + vloc;
            if (v < FV_DHW) {
                const float2 f2 = make_float2(tile[2 * c2][vloc], tile[2 * c2 + 1][vloc]);
                outp[(size_t)v * 16 + c2] = __float22half2_rn(f2);
            }
        }
    }
}

// Accumulate one corner: 8B load (4 fp16 channels), fp32 fmaf.
static __device__ __forceinline__ void fv_acc_corner(
    float4& acc, const uint2* __restrict__ f, int vox, float wgt
) {
    uint2 u = __ldg(&f[(size_t)vox * 8]);
    const __half2 h0 = *reinterpret_cast<const __half2*>(&u.x);
    const __half2 h1 = *reinterpret_cast<const __half2*>(&u.y);
    const float2 a = __half22float2(h0);
    const float2 b = __half22float2(h1);
    acc.x = fmaf(wgt, a.x, acc.x);
    acc.y = fmaf(wgt, a.y, acc.y);
    acc.z = fmaf(wgt, b.x, acc.z);
    acc.w = fmaf(wgt, b.y, acc.w);
}

// ---------------------------------------------------------------------------
// Sample: 8 threads per point; thread g owns channels [4g, 4g+4). Each corner:
// one LDG.64 per thread; the 8-thread group covers the 64B corner record.
// Output: streaming STG.128 (__stcs, evict-first) so the 128MB out-stream does
// not evict the ~131MB volume from L2. Coords: __ldcs (read once).
// ---------------------------------------------------------------------------
__global__ __launch_bounds__(256) void fv_sample_kernel(
    const float* __restrict__ xs,   // [N, 3] coords
    float4* __restrict__ out,       // [N, 8] float4 == [N, 32] float
    int n
) {
    const int t    = blockIdx.x * blockDim.x + threadIdx.x;
    const int p    = t >> 3;
    const int g    = t & 7;                 // channel group within point
    const int lane = threadIdx.x & 31;
    const int base = lane & ~7;             // first lane of this point's group

    // Cooperative coord load: lane r in [0,3) of each group loads component r.
    float cload = 0.0f;
    if (p < n && g < 3) cload = __ldcs(xs + 3 * (size_t)p + g);
    const float cx = __shfl_sync(0xffffffffu, cload, base + 0);  // -> W
    const float cy = __shfl_sync(0xffffffffu, cload, base + 1);  // -> H
    const float cz = __shfl_sync(0xffffffffu, cload, base + 2);  // -> D
    if (p >= n) return;

    // align_corners=True, border padding: i = clamp((c+1)*0.5*(S-1), 0, S-1)
    const float fx = fminf(fmaxf((cx + 1.0f) * 64.0f, 0.0f), 128.0f);
    const float fy = fminf(fmaxf((cy + 1.0f) * 64.0f, 0.0f), 128.0f);
    const float fz = fminf(fmaxf((cz + 1.0f) * 64.0f, 0.0f), 128.0f);

    const int x0 = (int)floorf(fx);
    const int y0 = (int)floorf(fy);
    const int z0 = (int)floorf(fz);
    const float tx = fx - (float)x0;
    const float ty = fy - (float)y0;
    const float tz = fz - (float)z0;
    const int x1 = min(x0 + 1, 128);
    const int y1 = min(y0 + 1, 128);
    const int z1 = min(z0 + 1, 128);

    const float wx0 = 1.0f - tx, wx1 = tx;
    const float wy0 = 1.0f - ty, wy1 = ty;
    const float wz0 = 1.0f - tz, wz1 = tz;

    // Row bases in voxel units: voxel(z,y,x) = (z*129 + y)*129 + x
    const int r00 = (z0 * FV_S + y0) * FV_S;
    const int r01 = (z0 * FV_S + y1) * FV_S;
    const int r10 = (z1 * FV_S + y0) * FV_S;
    const int r11 = (z1 * FV_S + y1) * FV_S;

    // uint2 (8B = 4 fp16) view offset by this thread's channel group.
    const uint2* __restrict__ f = reinterpret_cast<const uint2*>(g_fmT) + g;

    float4 acc = make_float4(0.0f, 0.0f, 0.0f, 0.0f);

    fv_acc_corner(acc, f, r00 + x0, wz0 * wy0 * wx0);
    fv_acc_corner(acc, f, r00 + x1, wz0 * wy0 * wx1);
    fv_acc_corner(acc, f, r01 + x0, wz0 * wy1 * wx0);
    fv_acc_corner(acc, f, r01 + x1, wz0 * wy1 * wx1);
    fv_acc_corner(acc, f, r10 + x0, wz1 * wy0 * wx0);
    fv_acc_corner(acc, f, r10 + x1, wz1 * wy0 * wx1);
    fv_acc_corner(acc, f, r11 + x0, wz1 * wy1 * wx0);
    fv_acc_corner(acc, f, r11 + x1, wz1 * wy1 * wx1);

    __stcs(&out[(size_t)p * 8 + g], acc);   // streaming: don't pollute L2
}

extern "C" void kernel_launch(void* const* d_in, const int* in_sizes, int n_in,
                              void* d_out, int out_size) {
    const float* x  = (const float*)d_in[0];   // [N, 3]
    const float* fm = (const float*)d_in[1];   // [32, 129, 129, 129]
    const int n = in_sizes[0] / 3;

    // 1) Transpose + fp16 quantize to channel-last scratch (every replay).
    fv_transpose_kernel<<<(FV_DHW + TVOX - 1) / TVOX, dim3(32, 8)>>>(fm);

    // 2) Gather + trilinear blend. 8 threads per point.
    const int total = n * 8;
    fv_sample_kernel<<<(total + 255) / 256, 256>>>(x, (float4*)d_out, n);
}